// round 6
// baseline (speedup 1.0000x reference)
#include <cuda_runtime.h>
#include <math.h>

#define Bb   8
#define Ss   4096
#define Dd   32
#define Nst  16
#define HIDn 128
#define Ll   64
#define CPB  64
#define NCHUNK 512
#define NGRP 8
#define GL   8
#define TOK  32768
#define OUT_ELEMS ((size_t)TOK*Dd*Dd)

// ---------------- scratch ----------------------------------------------------
__device__ float g_P   [NCHUNK*Nst];
__device__ float g_sL  [NCHUNK*512];
__device__ float g_yloc[TOK*Dd];
__device__ float g_cpi [TOK*Nst];
__device__ float g_hinL[NCHUNK*512];
__device__ float g_Hg  [Bb*NGRP*512];
__device__ float g_Plp [Bb*NGRP*GL*Nst];
__device__ float g_SxP [NCHUNK*Dd];
__device__ float g_SxxP[NCHUNK];
__device__ float g_lossB[Bb];

// ---------------- KA: fused projections + chunk scan -------------------------
// block = 128 threads = 4 warps; one chunk (64 tokens); grid = 512.
__global__ __launch_bounds__(128) void kA(
    const float* __restrict__ x,   const float* __restrict__ A,
    const float* __restrict__ Win, const float* __restrict__ binp,
    const float* __restrict__ Wdt, const float* __restrict__ bdt,
    const float* __restrict__ Wdtr,
    const float* __restrict__ WB,  const float* __restrict__ WC)
{
    __shared__ __align__(16) float sWin[Dd*Dd];
    __shared__ __align__(16) float sWB[Dd*Nst], sWC[Dd*Nst];
    __shared__ float sweff[Dd], sA[Nst], sbin[Dd], sSx[Dd];
    __shared__ float sSxx, sc0;
    __shared__ __align__(16) float sx [Ll*Dd];     // xp
    __shared__ __align__(16) float sa [Ll*Nst];
    __shared__ __align__(16) float sbd[Ll*Nst];
    __shared__ __align__(16) float scc[Ll*Nst];

    int tid = threadIdx.x;
    int ch  = blockIdx.x;
    size_t t0 = (size_t)ch * Ll;

    for (int i = tid; i < Dd*Dd;  i += 128) sWin[i] = Win[i];
    for (int i = tid; i < Dd*Nst; i += 128) { sWB[i] = WB[i]; sWC[i] = WC[i]; }
    if (tid < Dd) {
        float s = 0.f;
        #pragma unroll
        for (int r = 0; r < Nst; r++) s += Wdt[tid*Nst + r] * Wdtr[r];
        sweff[tid] = s;
        sbin[tid]  = binp[tid];
        sSx[tid]   = 0.f;
    }
    if (tid == 32) {
        float s = 0.f;
        #pragma unroll
        for (int r = 0; r < Nst; r++) s += bdt[r] * Wdtr[r];
        sc0 = s;
    }
    if (tid == 33) sSxx = 0.f;
    if (tid >= 40 && tid < 40 + Nst) sA[tid-40] = A[tid-40];
    __syncthreads();

    int warp = tid >> 5, lane = tid & 31, ln = lane & 15;

    // ---- phase A: projections, 16 tokens per warp ----
    float xsum = 0.f, xsq = 0.f;
    for (int i = 0; i < 16; i++) {
        int tl = warp*16 + i;
        float xv = x[(t0 + tl)*Dd + lane];
        xsum += xv; xsq += xv*xv;

        float xp = sbin[lane];
        #pragma unroll
        for (int k = 0; k < Dd; k++) {
            float xk = __shfl_sync(0xffffffffu, xv, k);
            xp += xk * sWin[k*Dd + lane];
        }

        float part = xp * sweff[lane];
        #pragma unroll
        for (int m = 16; m >= 1; m >>= 1) part += __shfl_xor_sync(0xffffffffu, part, m);
        float zz = part + sc0;
        float dt = fmaxf(zz, 0.f) + log1pf(expf(-fabsf(zz)));

        const float* Wsel = (lane < 16) ? sWB : sWC;
        float acc = 0.f;
        #pragma unroll
        for (int k = 0; k < Dd; k++) {
            float xpk = __shfl_sync(0xffffffffu, xp, k);
            acc += xpk * Wsel[k*Nst + ln];
        }

        sx[tl*Dd + lane] = xp;
        if (lane < 16) {
            sa [tl*Nst + ln] = expf(dt * sA[ln]);
            sbd[tl*Nst + ln] = dt * acc;
        } else {
            scc[tl*Nst + ln] = acc;
        }
    }

    atomicAdd(&sSx[lane], xsum);
    #pragma unroll
    for (int m = 16; m >= 1; m >>= 1) xsq += __shfl_xor_sync(0xffffffffu, xsq, m);
    if (lane == 0) atomicAdd(&sSxx, xsq);
    __syncthreads();

    if (tid < Dd)  g_SxP[ch*Dd + tid] = sSx[tid];
    if (tid == 32) g_SxxP[ch] = sSxx;

    // ---- phase B: warp 0 scans the chunk, h[16] in regs, lane = d ----
    if (warp == 0) {
        const float4* a4 = (const float4*)sa;
        const float4* b4 = (const float4*)sbd;
        const float4* c4 = (const float4*)scc;

        float h[16];
        #pragma unroll
        for (int n = 0; n < 16; n++) h[n] = 0.f;
        float pis = 1.f;

        float* yout = g_yloc + t0*Dd + lane;
        float* cpio = g_cpi  + t0*Nst;

        #pragma unroll 2
        for (int t = 0; t < Ll; t++) {
            float av[16], bv[16], cv[16];
            *(float4*)&av[0]  = a4[t*4+0]; *(float4*)&av[4]  = a4[t*4+1];
            *(float4*)&av[8]  = a4[t*4+2]; *(float4*)&av[12] = a4[t*4+3];
            *(float4*)&bv[0]  = b4[t*4+0]; *(float4*)&bv[4]  = b4[t*4+1];
            *(float4*)&bv[8]  = b4[t*4+2]; *(float4*)&bv[12] = b4[t*4+3];
            *(float4*)&cv[0]  = c4[t*4+0]; *(float4*)&cv[4]  = c4[t*4+1];
            *(float4*)&cv[8]  = c4[t*4+2]; *(float4*)&cv[12] = c4[t*4+3];
            float xv = sx[t*Dd + lane];

            float y0 = 0.f, y1 = 0.f, y2 = 0.f, y3 = 0.f;
            #pragma unroll
            for (int n = 0; n < 16; n += 4) {
                h[n+0] = fmaf(av[n+0], h[n+0], bv[n+0]*xv); y0 = fmaf(cv[n+0], h[n+0], y0);
                h[n+1] = fmaf(av[n+1], h[n+1], bv[n+1]*xv); y1 = fmaf(cv[n+1], h[n+1], y1);
                h[n+2] = fmaf(av[n+2], h[n+2], bv[n+2]*xv); y2 = fmaf(cv[n+2], h[n+2], y2);
                h[n+3] = fmaf(av[n+3], h[n+3], bv[n+3]*xv); y3 = fmaf(cv[n+3], h[n+3], y3);
            }
            yout[t*Dd] = (y0 + y1) + (y2 + y3);

            pis *= sa[t*Nst + ln];
            if (lane < 16) cpio[t*Nst + lane] = scc[t*Nst + lane] * pis;
        }

        float4* outL = (float4*)g_sL + (size_t)ch*128 + lane*4;
        outL[0] = make_float4(h[0],h[1],h[2],h[3]);
        outL[1] = make_float4(h[4],h[5],h[6],h[7]);
        outL[2] = make_float4(h[8],h[9],h[10],h[11]);
        outL[3] = make_float4(h[12],h[13],h[14],h[15]);
        if (lane < 16) g_P[ch*Nst + lane] = pis;
    }
}

// ---------------- K3: full per-batch combine + fused MLP loss ---------------
// grid = 8 (one per batch), block = 512.
__global__ __launch_bounds__(512) void k3(
    const float* __restrict__ Wd1, const float* __restrict__ bd1,
    const float* __restrict__ Wd2, const float* __restrict__ bd2,
    const float* __restrict__ Wd3, const float* __restrict__ bd3)
{
    __shared__ float sgend[NGRP*512];
    __shared__ float sPg[NGRP*Nst];
    __shared__ float sh[512];
    __shared__ float hrep[Nst], z1[HIDn], z2[HIDn], uu[Dd];
    __shared__ float sSxb[Dd], sSxxb;

    int b = blockIdx.x, off = threadIdx.x, n = off & 15;

    // level A: per-group combine (loads batched within group; groups pipelined)
    #pragma unroll
    for (int g = 0; g < NGRP; g++) {
        float lp[GL], ls[GL];
        #pragma unroll
        for (int j = 0; j < GL; j++) {
            int c = b*CPB + g*GL + j;
            lp[j] = g_P [c*Nst + n];
            ls[j] = g_sL[(size_t)c*512 + off];
        }
        float h = 0.f, pl = 1.f;
        #pragma unroll
        for (int j = 0; j < GL; j++) {
            int c = b*CPB + g*GL + j;
            g_hinL[(size_t)c*512 + off] = h;
            if (off < 16) g_Plp[((b*NGRP+g)*GL + j)*Nst + off] = pl;
            h  = fmaf(lp[j], h, ls[j]);
            pl *= lp[j];
        }
        sgend[g*512 + off] = h;
        if (off < 16) sPg[g*Nst + off] = pl;
    }
    __syncthreads();

    // level B: cross-group combine
    {
        float pg[NGRP], ge[NGRP];
        #pragma unroll
        for (int g = 0; g < NGRP; g++) {
            pg[g] = sPg[g*Nst + n];
            ge[g] = sgend[g*512 + off];
        }
        float h = 0.f;
        #pragma unroll
        for (int g = 0; g < NGRP; g++) {
            g_Hg[(size_t)(b*NGRP+g)*512 + off] = h;
            h = fmaf(pg[g], h, ge[g]);
        }
        sh[off] = h;
    }

    // loss-stat reduction (chunk partials)
    if (off < Dd) {
        float s = 0.f;
        #pragma unroll 8
        for (int k = 0; k < CPB; k++) s += g_SxP[(b*CPB + k)*Dd + off];
        sSxb[off] = s;
    } else if (off >= 32 && off < 64) {
        int l = off - 32;
        float s = g_SxxP[b*CPB + l] + g_SxxP[b*CPB + 32 + l];
        #pragma unroll
        for (int m = 16; m >= 1; m >>= 1) s += __shfl_xor_sync(0xffffffffu, s, m);
        if (l == 0) sSxxb = s;
    }
    __syncthreads();

    // MLP head
    if (off < Nst) {
        float s = 0.f;
        #pragma unroll
        for (int d = 0; d < Dd; d++) s += sh[d*Nst + off];
        hrep[off] = s * (1.f/(float)Dd);
    }
    __syncthreads();
    if (off < HIDn) {
        float acc = bd1[off];
        #pragma unroll
        for (int nn = 0; nn < Nst; nn++) acc += hrep[nn] * Wd1[nn*HIDn + off];
        z1[off] = fmaxf(acc, 0.f);
    }
    __syncthreads();
    if (off < HIDn) {
        float acc = bd2[off];
        #pragma unroll 8
        for (int j = 0; j < HIDn; j++) acc += z1[j] * Wd2[j*HIDn + off];
        z2[off] = fmaxf(acc, 0.f);
    }
    __syncthreads();
    if (off < Dd) {
        float acc = bd3[off];
        #pragma unroll 8
        for (int j = 0; j < HIDn; j++) acc += z2[j] * Wd3[j*Dd + off];
        uu[off] = acc;
    }
    __syncthreads();
    if (off == 0) {
        float t1 = 0.f, t2 = 0.f;
        #pragma unroll
        for (int d = 0; d < Dd; d++) {
            t1 += uu[d]*uu[d];
            t2 += uu[d]*sSxb[d];
        }
        g_lossB[b] = (float)Ss * t1 - 2.f*t2 + sSxxb;
    }
}

// ---------------- K4: block-per-chunk y recombine + streaming expansion -----
// grid = 512 (chunks), block = 512.
__global__ __launch_bounds__(512) void k4(
    const float* __restrict__ Wout, const float* __restrict__ bout,
    float* __restrict__ out, long long out_size)
{
    __shared__ float shin[Dd*17];        // padded stride 17: bank-conflict-free
    __shared__ float scpi[Ll*Nst];       // 1024
    __shared__ float sy[Ll*Dd];          // 2048
    __shared__ float4 sw[8], sb[8];

    int tid = threadIdx.x, ch = blockIdx.x;
    int bg = ch >> 3, j = ch & 7;

    // compose h_in = hinL + Plp * Hg  (one element per thread)
    {
        int d = tid >> 4, n = tid & 15;
        shin[d*17 + n] = fmaf(g_Plp[(bg*GL + j)*Nst + n],
                              g_Hg[(size_t)bg*512 + tid],
                              g_hinL[(size_t)ch*512 + tid]);
    }
    scpi[tid]       = g_cpi[(size_t)ch*1024 + tid];
    scpi[tid + 512] = g_cpi[(size_t)ch*1024 + 512 + tid];
    if (tid < 8)       sw[tid]   = ((const float4*)Wout)[tid];
    else if (tid < 16) sb[tid-8] = ((const float4*)bout)[tid-8];
    __syncthreads();

    // y[t,d] = y_local + sum_n cpi[t,n] * h_in[d,n]
    #pragma unroll
    for (int k = 0; k < 4; k++) {
        int idx = tid + k*512;
        int t = idx >> 5, d = idx & 31;
        float y = g_yloc[(size_t)ch*2048 + idx];
        #pragma unroll
        for (int n = 0; n < Nst; n++)
            y = fmaf(scpi[t*Nst + n], shin[d*17 + n], y);
        sy[idx] = y;
    }
    __syncthreads();

    // streaming expansion: 64 tokens * 1024 floats = 16384 float4
    {
        int q = tid & 7, r0 = tid >> 3;
        float4 w4 = sw[q], b4 = sb[q];
        float4* o = (float4*)out + (size_t)ch*16384;
        #pragma unroll
        for (int k = 0; k < 32; k++) {
            int r = r0 + k*64;
            float y = sy[r];
            float4 v;
            v.x = fmaf(y, w4.x, b4.x);
            v.y = fmaf(y, w4.y, b4.y);
            v.z = fmaf(y, w4.z, b4.z);
            v.w = fmaf(y, w4.w, b4.w);
            __stcs(&o[r*8 + q], v);
        }
    }

    if (ch == 0 && tid == 0 && out_size > (long long)OUT_ELEMS) {
        float s = 0.f;
        #pragma unroll
        for (int b = 0; b < Bb; b++) s += g_lossB[b];
        out[out_size - 1] = s * (1.f/(float)(Bb*Ss));
    }
}

// ---------------- launch -----------------------------------------------------
extern "C" void kernel_launch(void* const* d_in, const int* in_sizes, int n_in,
                              void* d_out, int out_size)
{
    const float* x    = (const float*)d_in[0];
    const float* A    = (const float*)d_in[1];
    const float* Win  = (const float*)d_in[2];
    const float* binp = (const float*)d_in[3];
    const float* Wdt  = (const float*)d_in[4];
    const float* bdt  = (const float*)d_in[5];
    const float* Wdtr = (const float*)d_in[6];
    const float* WB   = (const float*)d_in[7];
    const float* WC   = (const float*)d_in[8];
    const float* Wout = (const float*)d_in[9];
    const float* bout = (const float*)d_in[10];
    const float* Wd1  = (const float*)d_in[11];
    const float* bd1  = (const float*)d_in[12];
    const float* Wd2  = (const float*)d_in[13];
    const float* bd2  = (const float*)d_in[14];
    const float* Wd3  = (const float*)d_in[15];
    const float* bd3  = (const float*)d_in[16];
    float* out = (float*)d_out;

    kA<<<NCHUNK, 128>>>(x, A, Win, binp, Wdt, bdt, Wdtr, WB, WC);
    k3<<<Bb, 512>>>(Wd1, bd1, Wd2, bd2, Wd3, bd3);
    k4<<<NCHUNK, 512>>>(Wout, bout, out, (long long)out_size);
}

// round 9
// speedup vs baseline: 1.1515x; 1.1515x over previous
#include <cuda_runtime.h>
#include <math.h>

#define Bb   8
#define Ss   4096
#define Dd   32
#define Nst  16
#define HIDn 128
#define Ll   64
#define CPB  64
#define NCHUNK 512
#define NGRP 8
#define GL   8
#define TOK  32768
#define NBLK1 256                 // k1 blocks (128 tokens each)
#define OUT_ELEMS ((size_t)TOK*Dd*Dd)

// ---------------- scratch ----------------------------------------------------
__device__ float g_xp  [TOK*Dd];
__device__ float g_a   [TOK*Nst];
__device__ float g_bd  [TOK*Nst];
__device__ float g_c   [TOK*Nst];
__device__ float g_P   [NCHUNK*Nst];
__device__ float g_sL  [NCHUNK*512];
__device__ float g_yloc[TOK*Dd];
__device__ float g_cpi [TOK*Nst];
__device__ float g_hinL[NCHUNK*512];
__device__ float g_Hg  [Bb*NGRP*512];
__device__ float g_Plp [Bb*NGRP*GL*Nst];
__device__ float g_lossB[Bb];

// ---------------- K1: thread-per-token projections (no shuffles) -------------
// block = 128 threads = 128 tokens; grid = 256.
__global__ __launch_bounds__(128) void k1(
    const float* __restrict__ x,   const float* __restrict__ A,
    const float* __restrict__ Win, const float* __restrict__ binp,
    const float* __restrict__ Wdt, const float* __restrict__ bdt,
    const float* __restrict__ Wdtr,
    const float* __restrict__ WB,  const float* __restrict__ WC)
{
    __shared__ __align__(16) float4 sWin[Dd*8];     // [k][j] row-major
    __shared__ __align__(16) float4 sWB[Dd*4], sWC[Dd*4];
    __shared__ __align__(16) float4 sbin[8];
    __shared__ float sweff[Dd], sA[Nst];
    __shared__ float sc0;

    int tid = threadIdx.x;

    for (int i = tid; i < Dd*8; i += 128) sWin[i] = ((const float4*)Win)[i];
    for (int i = tid; i < Dd*4; i += 128) { sWB[i] = ((const float4*)WB)[i];
                                            sWC[i] = ((const float4*)WC)[i]; }
    if (tid < 8) sbin[tid] = ((const float4*)binp)[tid];
    if (tid < Dd) {
        float s = 0.f;
        #pragma unroll
        for (int r = 0; r < Nst; r++) s += Wdt[tid*Nst + r] * Wdtr[r];
        sweff[tid] = s;
    }
    if (tid == 32) {
        float s = 0.f;
        #pragma unroll
        for (int r = 0; r < Nst; r++) s += bdt[r] * Wdtr[r];
        sc0 = s;
    }
    if (tid >= 64 && tid < 64 + Nst) sA[tid-64] = A[tid-64];
    __syncthreads();

    int token = blockIdx.x * 128 + tid;

    // load x[32]
    float xr[32];
    {
        const float4* xg = (const float4*)x + (size_t)token*8;
        #pragma unroll
        for (int j = 0; j < 8; j++) {
            float4 v = xg[j];
            xr[j*4+0] = v.x; xr[j*4+1] = v.y; xr[j*4+2] = v.z; xr[j*4+3] = v.w;
        }
    }

    // xp = x @ Win + bin
    float xp[32];
    #pragma unroll
    for (int j = 0; j < 8; j++) {
        float4 b = sbin[j];
        xp[j*4+0] = b.x; xp[j*4+1] = b.y; xp[j*4+2] = b.z; xp[j*4+3] = b.w;
    }
    #pragma unroll
    for (int k = 0; k < 32; k++) {
        float xk = xr[k];
        #pragma unroll
        for (int j = 0; j < 8; j++) {
            float4 w = sWin[k*8+j];
            xp[j*4+0] = fmaf(xk, w.x, xp[j*4+0]);
            xp[j*4+1] = fmaf(xk, w.y, xp[j*4+1]);
            xp[j*4+2] = fmaf(xk, w.z, xp[j*4+2]);
            xp[j*4+3] = fmaf(xk, w.w, xp[j*4+3]);
        }
    }

    // dt = softplus(xp . weff + c0)
    float zz = sc0;
    #pragma unroll
    for (int k = 0; k < 32; k++) zz = fmaf(xp[k], sweff[k], zz);
    float dt = fmaxf(zz, 0.f) + log1pf(expf(-fabsf(zz)));

    // B and C projections
    float bb[16], cc[16];
    #pragma unroll
    for (int n = 0; n < 16; n++) { bb[n] = 0.f; cc[n] = 0.f; }
    #pragma unroll
    for (int k = 0; k < 32; k++) {
        float xpk = xp[k];
        #pragma unroll
        for (int j = 0; j < 4; j++) {
            float4 wb = sWB[k*4+j], wc = sWC[k*4+j];
            bb[j*4+0] = fmaf(xpk, wb.x, bb[j*4+0]);
            bb[j*4+1] = fmaf(xpk, wb.y, bb[j*4+1]);
            bb[j*4+2] = fmaf(xpk, wb.z, bb[j*4+2]);
            bb[j*4+3] = fmaf(xpk, wb.w, bb[j*4+3]);
            cc[j*4+0] = fmaf(xpk, wc.x, cc[j*4+0]);
            cc[j*4+1] = fmaf(xpk, wc.y, cc[j*4+1]);
            cc[j*4+2] = fmaf(xpk, wc.z, cc[j*4+2]);
            cc[j*4+3] = fmaf(xpk, wc.w, cc[j*4+3]);
        }
    }

    // stores
    {
        float4* o = (float4*)g_xp + (size_t)token*8;
        #pragma unroll
        for (int j = 0; j < 8; j++)
            o[j] = make_float4(xp[j*4+0], xp[j*4+1], xp[j*4+2], xp[j*4+3]);
    }
    {
        float4* oa = (float4*)g_a  + (size_t)token*4;
        float4* ob = (float4*)g_bd + (size_t)token*4;
        float4* oc = (float4*)g_c  + (size_t)token*4;
        #pragma unroll
        for (int j = 0; j < 4; j++) {
            float4 av;
            av.x = expf(dt * sA[j*4+0]);
            av.y = expf(dt * sA[j*4+1]);
            av.z = expf(dt * sA[j*4+2]);
            av.w = expf(dt * sA[j*4+3]);
            oa[j] = av;
            ob[j] = make_float4(dt*bb[j*4+0], dt*bb[j*4+1], dt*bb[j*4+2], dt*bb[j*4+3]);
            oc[j] = make_float4(cc[j*4+0], cc[j*4+1], cc[j*4+2], cc[j*4+3]);
        }
    }
}

// ---------------- K2: warp-per-chunk scan; emits sL, P, y_local, cpi --------
// block = 64 threads = 2 warps = 2 chunks; lane = d; grid = 256.
__global__ __launch_bounds__(64) void k2_scan(void)
{
    __shared__ float4 s4[2*1280];
    int tid = threadIdx.x;
    int chunk0 = blockIdx.x * 2;

    for (int cc = 0; cc < 2; cc++) {
        int ch = chunk0 + cc;
        const float4* pa = (const float4*)g_a  + (size_t)ch*256;
        const float4* pb = (const float4*)g_bd + (size_t)ch*256;
        const float4* pc = (const float4*)g_c  + (size_t)ch*256;
        const float4* px = (const float4*)g_xp + (size_t)ch*512;
        float4* s = s4 + cc*1280;
        for (int i = tid; i < 256; i += 64) { s[i] = pa[i]; s[256+i] = pb[i]; s[512+i] = pc[i]; }
        for (int i = tid; i < 512; i += 64) s[768+i] = px[i];
    }
    __syncthreads();

    int warp = tid >> 5, lane = tid & 31;
    int ch = chunk0 + warp;
    const float4* s  = s4 + warp*1280;
    const float*  sa = (const float*)s;
    const float*  sc = (const float*)(s + 512);
    const float*  sx = (const float*)(s + 768);
    int nl = lane & 15;

    float h[16];
    #pragma unroll
    for (int n = 0; n < 16; n++) h[n] = 0.f;
    float pis = 1.f;

    float* yout = g_yloc + (size_t)ch*Ll*Dd + lane;
    float* cpio = g_cpi  + (size_t)ch*Ll*Nst;

    #pragma unroll 2
    for (int t = 0; t < Ll; t++) {
        float av[16], bv[16], cv[16];
        *(float4*)&av[0]  = s[t*4+0];     *(float4*)&av[4]  = s[t*4+1];
        *(float4*)&av[8]  = s[t*4+2];     *(float4*)&av[12] = s[t*4+3];
        *(float4*)&bv[0]  = s[256+t*4+0]; *(float4*)&bv[4]  = s[256+t*4+1];
        *(float4*)&bv[8]  = s[256+t*4+2]; *(float4*)&bv[12] = s[256+t*4+3];
        *(float4*)&cv[0]  = s[512+t*4+0]; *(float4*)&cv[4]  = s[512+t*4+1];
        *(float4*)&cv[8]  = s[512+t*4+2]; *(float4*)&cv[12] = s[512+t*4+3];
        float xv = sx[t*32 + lane];

        float y0 = 0.f, y1 = 0.f, y2 = 0.f, y3 = 0.f;
        #pragma unroll
        for (int n = 0; n < 16; n += 4) {
            h[n+0] = fmaf(av[n+0], h[n+0], bv[n+0]*xv); y0 = fmaf(cv[n+0], h[n+0], y0);
            h[n+1] = fmaf(av[n+1], h[n+1], bv[n+1]*xv); y1 = fmaf(cv[n+1], h[n+1], y1);
            h[n+2] = fmaf(av[n+2], h[n+2], bv[n+2]*xv); y2 = fmaf(cv[n+2], h[n+2], y2);
            h[n+3] = fmaf(av[n+3], h[n+3], bv[n+3]*xv); y3 = fmaf(cv[n+3], h[n+3], y3);
        }
        yout[t*Dd] = (y0 + y1) + (y2 + y3);

        pis *= sa[t*16 + nl];
        if (lane < 16) cpio[t*Nst + lane] = sc[t*16 + lane] * pis;
    }

    float4* outL = (float4*)g_sL + (size_t)ch*128 + lane*4;
    outL[0] = make_float4(h[0],h[1],h[2],h[3]);
    outL[1] = make_float4(h[4],h[5],h[6],h[7]);
    outL[2] = make_float4(h[8],h[9],h[10],h[11]);
    outL[3] = make_float4(h[12],h[13],h[14],h[15]);
    if (lane < 16) g_P[ch*Nst + lane] = pis;
}

// ---------------- K3: per-batch combine + loss stats from x + MLP loss ------
// grid = 8 (one per batch), block = 512.
__global__ __launch_bounds__(512) void k3(
    const float* __restrict__ x,
    const float* __restrict__ Wd1, const float* __restrict__ bd1,
    const float* __restrict__ Wd2, const float* __restrict__ bd2,
    const float* __restrict__ Wd3, const float* __restrict__ bd3)
{
    __shared__ float sgend[NGRP*512];
    __shared__ float sPg[NGRP*Nst];
    __shared__ float sh[512];
    __shared__ float sPart[512];         // per-(group,d) partial Sx
    __shared__ float sSqW[16];           // per-warp Sxx partials
    __shared__ float hrep[Nst], z1[HIDn], z2[HIDn], uu[Dd];
    __shared__ float sSxb[Dd], sSxxb;

    int b = blockIdx.x, off = threadIdx.x, n = off & 15;

    // level A: per-group combine
    #pragma unroll
    for (int g = 0; g < NGRP; g++) {
        float lp[GL], ls[GL];
        #pragma unroll
        for (int j = 0; j < GL; j++) {
            int c = b*CPB + g*GL + j;
            lp[j] = g_P [c*Nst + n];
            ls[j] = g_sL[(size_t)c*512 + off];
        }
        float h = 0.f, pl = 1.f;
        #pragma unroll
        for (int j = 0; j < GL; j++) {
            int c = b*CPB + g*GL + j;
            g_hinL[(size_t)c*512 + off] = h;
            if (off < 16) g_Plp[((b*NGRP+g)*GL + j)*Nst + off] = pl;
            h  = fmaf(lp[j], h, ls[j]);
            pl *= lp[j];
        }
        sgend[g*512 + off] = h;
        if (off < 16) sPg[g*Nst + off] = pl;
    }
    __syncthreads();

    // level B: cross-group combine
    {
        float pg[NGRP], ge[NGRP];
        #pragma unroll
        for (int g = 0; g < NGRP; g++) {
            pg[g] = sPg[g*Nst + n];
            ge[g] = sgend[g*512 + off];
        }
        float h = 0.f;
        #pragma unroll
        for (int g = 0; g < NGRP; g++) {
            g_Hg[(size_t)(b*NGRP+g)*512 + off] = h;
            h = fmaf(pg[g], h, ge[g]);
        }
        sh[off] = h;
    }

    // loss stats from x: Sx[d] = sum_s x[b,s,d], Sxx = sum x^2
    {
        int d = off & 31, grp = off >> 5;      // 16 token-groups
        const float* xb = x + (size_t)b*Ss*Dd;
        float s = 0.f, sq = 0.f;
        for (int tk = grp; tk < Ss; tk += 16) {
            float v = xb[(size_t)tk*Dd + d];
            s += v; sq = fmaf(v, v, sq);
        }
        sPart[grp*32 + d] = s;
        #pragma unroll
        for (int m = 16; m >= 1; m >>= 1) sq += __shfl_xor_sync(0xffffffffu, sq, m);
        if (d == 0) sSqW[grp] = sq;
    }
    __syncthreads();
    if (off < Dd) {
        float s = 0.f;
        #pragma unroll
        for (int g = 0; g < 16; g++) s += sPart[g*32 + off];
        sSxb[off] = s;
    }
    if (off == 32) {
        float s = 0.f;
        #pragma unroll
        for (int g = 0; g < 16; g++) s += sSqW[g];
        sSxxb = s;
    }
    __syncthreads();

    // MLP head
    if (off < Nst) {
        float s = 0.f;
        #pragma unroll
        for (int d = 0; d < Dd; d++) s += sh[d*Nst + off];
        hrep[off] = s * (1.f/(float)Dd);
    }
    __syncthreads();
    if (off < HIDn) {
        float acc = bd1[off];
        #pragma unroll
        for (int nn = 0; nn < Nst; nn++) acc += hrep[nn] * Wd1[nn*HIDn + off];
        z1[off] = fmaxf(acc, 0.f);
    }
    __syncthreads();
    if (off < HIDn) {
        float acc = bd2[off];
        #pragma unroll 8
        for (int j = 0; j < HIDn; j++) acc += z1[j] * Wd2[j*HIDn + off];
        z2[off] = fmaxf(acc, 0.f);
    }
    __syncthreads();
    if (off < Dd) {
        float acc = bd3[off];
        #pragma unroll 8
        for (int j = 0; j < HIDn; j++) acc += z2[j] * Wd3[j*Dd + off];
        uu[off] = acc;
    }
    __syncthreads();
    if (off == 0) {
        float t1 = 0.f, t2 = 0.f;
        #pragma unroll
        for (int d = 0; d < Dd; d++) {
            t1 += uu[d]*uu[d];
            t2 += uu[d]*sSxb[d];
        }
        g_lossB[b] = (float)Ss * t1 - 2.f*t2 + sSxxb;
    }
}

// ---------------- K4: block-per-chunk y recombine + streaming expansion -----
__global__ __launch_bounds__(512) void k4(
    const float* __restrict__ Wout, const float* __restrict__ bout,
    float* __restrict__ out, long long out_size)
{
    __shared__ float shin[Dd*17];
    __shared__ float scpi[Ll*Nst];
    __shared__ float sy[Ll*Dd];
    __shared__ float4 sw[8], sb[8];

    int tid = threadIdx.x, ch = blockIdx.x;
    int bg = ch >> 3, j = ch & 7;

    {
        int d = tid >> 4, n = tid & 15;
        shin[d*17 + n] = fmaf(g_Plp[(bg*GL + j)*Nst + n],
                              g_Hg[(size_t)bg*512 + tid],
                              g_hinL[(size_t)ch*512 + tid]);
    }
    scpi[tid]       = g_cpi[(size_t)ch*1024 + tid];
    scpi[tid + 512] = g_cpi[(size_t)ch*1024 + 512 + tid];
    if (tid < 8)       sw[tid]   = ((const float4*)Wout)[tid];
    else if (tid < 16) sb[tid-8] = ((const float4*)bout)[tid-8];
    __syncthreads();

    #pragma unroll
    for (int k = 0; k < 4; k++) {
        int idx = tid + k*512;
        int t = idx >> 5, d = idx & 31;
        float y = g_yloc[(size_t)ch*2048 + idx];
        #pragma unroll
        for (int n = 0; n < Nst; n++)
            y = fmaf(scpi[t*Nst + n], shin[d*17 + n], y);
        sy[idx] = y;
    }
    __syncthreads();

    {
        int q = tid & 7, r0 = tid >> 3;
        float4 w4 = sw[q], b4 = sb[q];
        float4* o = (float4*)out + (size_t)ch*16384;
        #pragma unroll
        for (int k = 0; k < 32; k++) {
            int r = r0 + k*64;
            float y = sy[r];
            float4 v;
            v.x = fmaf(y, w4.x, b4.x);
            v.y = fmaf(y, w4.y, b4.y);
            v.z = fmaf(y, w4.z, b4.z);
            v.w = fmaf(y, w4.w, b4.w);
            __stcs(&o[r*8 + q], v);
        }
    }

    if (ch == 0 && tid == 0 && out_size > (long long)OUT_ELEMS) {
        float s = 0.f;
        #pragma unroll
        for (int b = 0; b < Bb; b++) s += g_lossB[b];
        out[out_size - 1] = s * (1.f/(float)(Bb*Ss));
    }
}

// ---------------- launch -----------------------------------------------------
extern "C" void kernel_launch(void* const* d_in, const int* in_sizes, int n_in,
                              void* d_out, int out_size)
{
    const float* x    = (const float*)d_in[0];
    const float* A    = (const float*)d_in[1];
    const float* Win  = (const float*)d_in[2];
    const float* binp = (const float*)d_in[3];
    const float* Wdt  = (const float*)d_in[4];
    const float* bdt  = (const float*)d_in[5];
    const float* Wdtr = (const float*)d_in[6];
    const float* WB   = (const float*)d_in[7];
    const float* WC   = (const float*)d_in[8];
    const float* Wout = (const float*)d_in[9];
    const float* bout = (const float*)d_in[10];
    const float* Wd1  = (const float*)d_in[11];
    const float* bd1  = (const float*)d_in[12];
    const float* Wd2  = (const float*)d_in[13];
    const float* bd2  = (const float*)d_in[14];
    const float* Wd3  = (const float*)d_in[15];
    const float* bd3  = (const float*)d_in[16];
    float* out = (float*)d_out;

    k1     <<<NBLK1, 128>>>(x, A, Win, binp, Wdt, bdt, Wdtr, WB, WC);
    k2_scan<<<NCHUNK/2, 64>>>();
    k3     <<<Bb, 512>>>(x, Wd1, bd1, Wd2, bd2, Wd3, bd3);
    k4     <<<NCHUNK, 512>>>(Wout, bout, out, (long long)out_size);
}

// round 10
// speedup vs baseline: 1.3089x; 1.1367x over previous
#include <cuda_runtime.h>
#include <math.h>

#define Bb   8
#define Ss   4096
#define Dd   32
#define Nst  16
#define HIDn 128
#define Ll   64
#define CPB  64
#define NCHUNK 512
#define NGRP 8
#define GL   8
#define TOK  32768
#define OUT_ELEMS ((size_t)TOK*Dd*Dd)

// ---------------- scratch ----------------------------------------------------
__device__ float g_P   [NCHUNK*Nst];
__device__ float g_sL  [NCHUNK*512];
__device__ float g_yloc[TOK*Dd];
__device__ float g_cpi [TOK*Nst];
__device__ float g_hinL[NCHUNK*512];
__device__ float g_Hg  [Bb*NGRP*512];
__device__ float g_Plp [Bb*NGRP*GL*Nst];
__device__ float g_SxP [NCHUNK*Dd];
__device__ float g_SxxP[NCHUNK];
__device__ float g_lossB[Bb];

// ---------------- KP: fused thread-per-token projection + warp scan ---------
// block = 64 threads = one chunk (64 tokens); grid = 512.
// warps: both project; then warp0 scans from smem, warp1 does x-stats.
__global__ __launch_bounds__(64) void kP(
    const float* __restrict__ x,   const float* __restrict__ A,
    const float* __restrict__ Win, const float* __restrict__ binp,
    const float* __restrict__ Wdt, const float* __restrict__ bdt,
    const float* __restrict__ Wdtr,
    const float* __restrict__ WB,  const float* __restrict__ WC)
{
    // staging layout (float4): [a 256 | bd 256 | c 256 | x 512]
    __shared__ __align__(16) float4 sstage[1280];        // 20 KB
    __shared__ __align__(16) float4 sWin4[Dd*8];         // 4 KB
    __shared__ __align__(16) float4 sWB4[Dd*4], sWC4[Dd*4];
    __shared__ __align__(16) float4 sbin4[8];
    __shared__ float sweff[Dd], sA[Nst];
    __shared__ float sc0;

    int tid = threadIdx.x;
    int ch  = blockIdx.x;
    int token = ch*Ll + tid;

    for (int i = tid; i < Dd*8; i += 64) sWin4[i] = ((const float4*)Win)[i];
    for (int i = tid; i < Dd*4; i += 64) { sWB4[i] = ((const float4*)WB)[i];
                                           sWC4[i] = ((const float4*)WC)[i]; }
    if (tid < 8) sbin4[tid] = ((const float4*)binp)[tid];
    if (tid < Dd) {
        float s = 0.f;
        #pragma unroll
        for (int r = 0; r < Nst; r++) s += Wdt[tid*Nst + r] * Wdtr[r];
        sweff[tid] = s;
    }
    if (tid == 32) {
        float s = 0.f;
        #pragma unroll
        for (int r = 0; r < Nst; r++) s += bdt[r] * Wdtr[r];
        sc0 = s;
    }
    if (tid >= 40 && tid < 40 + Nst) sA[tid-40] = A[tid-40];
    __syncthreads();

    // ---- projection: each thread owns one token ----
    float xr[32];
    {
        const float4* xg = (const float4*)x + (size_t)token*8;
        #pragma unroll
        for (int j = 0; j < 8; j++) {
            float4 v = xg[j];
            xr[j*4+0] = v.x; xr[j*4+1] = v.y; xr[j*4+2] = v.z; xr[j*4+3] = v.w;
        }
    }

    float xp[32];
    #pragma unroll
    for (int j = 0; j < 8; j++) {
        float4 b = sbin4[j];
        xp[j*4+0] = b.x; xp[j*4+1] = b.y; xp[j*4+2] = b.z; xp[j*4+3] = b.w;
    }
    #pragma unroll
    for (int k = 0; k < 32; k++) {
        float xk = xr[k];
        #pragma unroll
        for (int j = 0; j < 8; j++) {
            float4 w = sWin4[k*8+j];
            xp[j*4+0] = fmaf(xk, w.x, xp[j*4+0]);
            xp[j*4+1] = fmaf(xk, w.y, xp[j*4+1]);
            xp[j*4+2] = fmaf(xk, w.z, xp[j*4+2]);
            xp[j*4+3] = fmaf(xk, w.w, xp[j*4+3]);
        }
    }

    float zz = sc0;
    #pragma unroll
    for (int k = 0; k < 32; k++) zz = fmaf(xp[k], sweff[k], zz);
    float dt = fmaxf(zz, 0.f) + log1pf(expf(-fabsf(zz)));

    float bb[16], cc[16];
    #pragma unroll
    for (int n = 0; n < 16; n++) { bb[n] = 0.f; cc[n] = 0.f; }
    #pragma unroll
    for (int k = 0; k < 32; k++) {
        float xpk = xp[k];
        #pragma unroll
        for (int j = 0; j < 4; j++) {
            float4 wb = sWB4[k*4+j], wc = sWC4[k*4+j];
            bb[j*4+0] = fmaf(xpk, wb.x, bb[j*4+0]);
            bb[j*4+1] = fmaf(xpk, wb.y, bb[j*4+1]);
            bb[j*4+2] = fmaf(xpk, wb.z, bb[j*4+2]);
            bb[j*4+3] = fmaf(xpk, wb.w, bb[j*4+3]);
            cc[j*4+0] = fmaf(xpk, wc.x, cc[j*4+0]);
            cc[j*4+1] = fmaf(xpk, wc.y, cc[j*4+1]);
            cc[j*4+2] = fmaf(xpk, wc.z, cc[j*4+2]);
            cc[j*4+3] = fmaf(xpk, wc.w, cc[j*4+3]);
        }
    }

    // stage into scan layout
    #pragma unroll
    for (int j = 0; j < 4; j++) {
        sstage[      tid*4 + j] = make_float4(expf(dt*sA[j*4+0]), expf(dt*sA[j*4+1]),
                                              expf(dt*sA[j*4+2]), expf(dt*sA[j*4+3]));
        sstage[256 + tid*4 + j] = make_float4(dt*bb[j*4+0], dt*bb[j*4+1],
                                              dt*bb[j*4+2], dt*bb[j*4+3]);
        sstage[512 + tid*4 + j] = make_float4(cc[j*4+0], cc[j*4+1], cc[j*4+2], cc[j*4+3]);
    }
    #pragma unroll
    for (int j = 0; j < 8; j++)
        sstage[768 + tid*8 + j] = make_float4(xp[j*4+0], xp[j*4+1], xp[j*4+2], xp[j*4+3]);
    __syncthreads();

    int warp = tid >> 5, lane = tid & 31;
    if (warp == 0) {
        // ---- scan: lane = d, h[16] in regs ----
        const float4* s  = sstage;
        const float*  sa = (const float*)s;
        const float*  sc = (const float*)(s + 512);
        const float*  sx = (const float*)(s + 768);
        int nl = lane & 15;

        float h[16];
        #pragma unroll
        for (int n = 0; n < 16; n++) h[n] = 0.f;
        float pis = 1.f;

        float* yout = g_yloc + (size_t)ch*Ll*Dd + lane;
        float* cpio = g_cpi  + (size_t)ch*Ll*Nst;

        #pragma unroll 2
        for (int t = 0; t < Ll; t++) {
            float av[16], bv[16], cv[16];
            *(float4*)&av[0]  = s[t*4+0];     *(float4*)&av[4]  = s[t*4+1];
            *(float4*)&av[8]  = s[t*4+2];     *(float4*)&av[12] = s[t*4+3];
            *(float4*)&bv[0]  = s[256+t*4+0]; *(float4*)&bv[4]  = s[256+t*4+1];
            *(float4*)&bv[8]  = s[256+t*4+2]; *(float4*)&bv[12] = s[256+t*4+3];
            *(float4*)&cv[0]  = s[512+t*4+0]; *(float4*)&cv[4]  = s[512+t*4+1];
            *(float4*)&cv[8]  = s[512+t*4+2]; *(float4*)&cv[12] = s[512+t*4+3];
            float xv = sx[t*32 + lane];

            float y0 = 0.f, y1 = 0.f, y2 = 0.f, y3 = 0.f;
            #pragma unroll
            for (int n = 0; n < 16; n += 4) {
                h[n+0] = fmaf(av[n+0], h[n+0], bv[n+0]*xv); y0 = fmaf(cv[n+0], h[n+0], y0);
                h[n+1] = fmaf(av[n+1], h[n+1], bv[n+1]*xv); y1 = fmaf(cv[n+1], h[n+1], y1);
                h[n+2] = fmaf(av[n+2], h[n+2], bv[n+2]*xv); y2 = fmaf(cv[n+2], h[n+2], y2);
                h[n+3] = fmaf(av[n+3], h[n+3], bv[n+3]*xv); y3 = fmaf(cv[n+3], h[n+3], y3);
            }
            yout[t*Dd] = (y0 + y1) + (y2 + y3);

            pis *= sa[t*16 + nl];
            if (lane < 16) cpio[t*Nst + lane] = sc[t*16 + lane] * pis;
        }

        float4* outL = (float4*)g_sL + (size_t)ch*128 + lane*4;
        outL[0] = make_float4(h[0],h[1],h[2],h[3]);
        outL[1] = make_float4(h[4],h[5],h[6],h[7]);
        outL[2] = make_float4(h[8],h[9],h[10],h[11]);
        outL[3] = make_float4(h[12],h[13],h[14],h[15]);
        if (lane < 16) g_P[ch*Nst + lane] = pis;
    } else {
        // ---- x statistics for this chunk (x is L2-resident) ----
        const float* xb = x + (size_t)ch*Ll*Dd;
        float s = 0.f, sq = 0.f;
        #pragma unroll 8
        for (int t = 0; t < Ll; t++) {
            float v = xb[t*Dd + lane];
            s += v; sq = fmaf(v, v, sq);
        }
        g_SxP[ch*Dd + lane] = s;
        #pragma unroll
        for (int m = 16; m >= 1; m >>= 1) sq += __shfl_xor_sync(0xffffffffu, sq, m);
        if (lane == 0) g_SxxP[ch] = sq;
    }
}

// ---------------- K3: per-batch combine + stat reduce + MLP loss ------------
// grid = 8 (one per batch), block = 512.
__global__ __launch_bounds__(512) void k3(
    const float* __restrict__ Wd1, const float* __restrict__ bd1,
    const float* __restrict__ Wd2, const float* __restrict__ bd2,
    const float* __restrict__ Wd3, const float* __restrict__ bd3)
{
    __shared__ float sgend[NGRP*512];
    __shared__ float sPg[NGRP*Nst];
    __shared__ float sh[512];
    __shared__ float hrep[Nst], z1[HIDn], z2[HIDn], uu[Dd];
    __shared__ float sSxb[Dd], sSxxb;

    int b = blockIdx.x, off = threadIdx.x, n = off & 15;

    // level A: per-group combine
    #pragma unroll
    for (int g = 0; g < NGRP; g++) {
        float lp[GL], ls[GL];
        #pragma unroll
        for (int j = 0; j < GL; j++) {
            int c = b*CPB + g*GL + j;
            lp[j] = g_P [c*Nst + n];
            ls[j] = g_sL[(size_t)c*512 + off];
        }
        float h = 0.f, pl = 1.f;
        #pragma unroll
        for (int j = 0; j < GL; j++) {
            int c = b*CPB + g*GL + j;
            g_hinL[(size_t)c*512 + off] = h;
            if (off < 16) g_Plp[((b*NGRP+g)*GL + j)*Nst + off] = pl;
            h  = fmaf(lp[j], h, ls[j]);
            pl *= lp[j];
        }
        sgend[g*512 + off] = h;
        if (off < 16) sPg[g*Nst + off] = pl;
    }
    __syncthreads();

    // level B: cross-group combine
    {
        float pg[NGRP], ge[NGRP];
        #pragma unroll
        for (int g = 0; g < NGRP; g++) {
            pg[g] = sPg[g*Nst + n];
            ge[g] = sgend[g*512 + off];
        }
        float h = 0.f;
        #pragma unroll
        for (int g = 0; g < NGRP; g++) {
            g_Hg[(size_t)(b*NGRP+g)*512 + off] = h;
            h = fmaf(pg[g], h, ge[g]);
        }
        sh[off] = h;
    }

    // stat reduce: 64 chunk-partials per batch
    if (off < Dd) {
        float s = 0.f;
        #pragma unroll 8
        for (int k = 0; k < CPB; k++) s += g_SxP[(b*CPB + k)*Dd + off];
        sSxb[off] = s;
    } else if (off >= 32 && off < 64) {
        int l = off - 32;
        float s = g_SxxP[b*CPB + l] + g_SxxP[b*CPB + 32 + l];
        #pragma unroll
        for (int m = 16; m >= 1; m >>= 1) s += __shfl_xor_sync(0xffffffffu, s, m);
        if (l == 0) sSxxb = s;
    }
    __syncthreads();

    // MLP head
    if (off < Nst) {
        float s = 0.f;
        #pragma unroll
        for (int d = 0; d < Dd; d++) s += sh[d*Nst + off];
        hrep[off] = s * (1.f/(float)Dd);
    }
    __syncthreads();
    if (off < HIDn) {
        float acc = bd1[off];
        #pragma unroll
        for (int nn = 0; nn < Nst; nn++) acc += hrep[nn] * Wd1[nn*HIDn + off];
        z1[off] = fmaxf(acc, 0.f);
    }
    __syncthreads();
    if (off < HIDn) {
        float acc = bd2[off];
        #pragma unroll 8
        for (int j = 0; j < HIDn; j++) acc += z1[j] * Wd2[j*HIDn + off];
        z2[off] = fmaxf(acc, 0.f);
    }
    __syncthreads();
    if (off < Dd) {
        float acc = bd3[off];
        #pragma unroll 8
        for (int j = 0; j < HIDn; j++) acc += z2[j] * Wd3[j*Dd + off];
        uu[off] = acc;
    }
    __syncthreads();
    if (off == 0) {
        float t1 = 0.f, t2 = 0.f;
        #pragma unroll
        for (int d = 0; d < Dd; d++) {
            t1 += uu[d]*uu[d];
            t2 += uu[d]*sSxb[d];
        }
        g_lossB[b] = (float)Ss * t1 - 2.f*t2 + sSxxb;
    }
}

// ---------------- K4: block-per-chunk y recombine + streaming expansion -----
__global__ __launch_bounds__(512) void k4(
    const float* __restrict__ Wout, const float* __restrict__ bout,
    float* __restrict__ out, long long out_size)
{
    __shared__ float shin[Dd*17];
    __shared__ float scpi[Ll*Nst];
    __shared__ float sy[Ll*Dd];
    __shared__ float4 sw[8], sb[8];

    int tid = threadIdx.x, ch = blockIdx.x;
    int bg = ch >> 3, j = ch & 7;

    {
        int d = tid >> 4, n = tid & 15;
        shin[d*17 + n] = fmaf(g_Plp[(bg*GL + j)*Nst + n],
                              g_Hg[(size_t)bg*512 + tid],
                              g_hinL[(size_t)ch*512 + tid]);
    }
    scpi[tid]       = g_cpi[(size_t)ch*1024 + tid];
    scpi[tid + 512] = g_cpi[(size_t)ch*1024 + 512 + tid];
    if (tid < 8)       sw[tid]   = ((const float4*)Wout)[tid];
    else if (tid < 16) sb[tid-8] = ((const float4*)bout)[tid-8];
    __syncthreads();

    #pragma unroll
    for (int k = 0; k < 4; k++) {
        int idx = tid + k*512;
        int t = idx >> 5, d = idx & 31;
        float y = g_yloc[(size_t)ch*2048 + idx];
        #pragma unroll
        for (int n = 0; n < Nst; n++)
            y = fmaf(scpi[t*Nst + n], shin[d*17 + n], y);
        sy[idx] = y;
    }
    __syncthreads();

    {
        int q = tid & 7, r0 = tid >> 3;
        float4 w4 = sw[q], b4 = sb[q];
        float4* o = (float4*)out + (size_t)ch*16384;
        #pragma unroll
        for (int k = 0; k < 32; k++) {
            int r = r0 + k*64;
            float y = sy[r];
            float4 v;
            v.x = fmaf(y, w4.x, b4.x);
            v.y = fmaf(y, w4.y, b4.y);
            v.z = fmaf(y, w4.z, b4.z);
            v.w = fmaf(y, w4.w, b4.w);
            __stcs(&o[r*8 + q], v);
        }
    }

    if (ch == 0 && tid == 0 && out_size > (long long)OUT_ELEMS) {
        float s = 0.f;
        #pragma unroll
        for (int b = 0; b < Bb; b++) s += g_lossB[b];
        out[out_size - 1] = s * (1.f/(float)(Bb*Ss));
    }
}

// ---------------- launch -----------------------------------------------------
extern "C" void kernel_launch(void* const* d_in, const int* in_sizes, int n_in,
                              void* d_out, int out_size)
{
    const float* x    = (const float*)d_in[0];
    const float* A    = (const float*)d_in[1];
    const float* Win  = (const float*)d_in[2];
    const float* binp = (const float*)d_in[3];
    const float* Wdt  = (const float*)d_in[4];
    const float* bdt  = (const float*)d_in[5];
    const float* Wdtr = (const float*)d_in[6];
    const float* WB   = (const float*)d_in[7];
    const float* WC   = (const float*)d_in[8];
    const float* Wout = (const float*)d_in[9];
    const float* bout = (const float*)d_in[10];
    const float* Wd1  = (const float*)d_in[11];
    const float* bd1  = (const float*)d_in[12];
    const float* Wd2  = (const float*)d_in[13];
    const float* bd2  = (const float*)d_in[14];
    const float* Wd3  = (const float*)d_in[15];
    const float* bd3  = (const float*)d_in[16];
    float* out = (float*)d_out;

    kP<<<NCHUNK, 64>>>(x, A, Win, binp, Wdt, bdt, Wdtr, WB, WC);
    k3<<<Bb, 512>>>(Wd1, bd1, Wd2, bd2, Wd3, bd3);
    k4<<<NCHUNK, 512>>>(Wout, bout, out, (long long)out_size);
}

// round 11
// speedup vs baseline: 1.3167x; 1.0060x over previous
#include <cuda_runtime.h>
#include <math.h>

#define Bb   8
#define Ss   4096
#define Dd   32
#define Nst  16
#define HIDn 128
#define Ll   64
#define CPB  64
#define NCHUNK 512
#define NGRP 8
#define GL   8
#define TOK  32768
#define OUT_ELEMS ((size_t)TOK*Dd*Dd)

// ---------------- scratch ----------------------------------------------------
__device__ float g_P   [NCHUNK*Nst];
__device__ float g_sL  [NCHUNK*512];
__device__ float g_yloc[TOK*Dd];
__device__ float g_cpi [TOK*Nst];
__device__ float g_hinL[NCHUNK*512];
__device__ float g_Hg  [Bb*NGRP*512];
__device__ float g_Plp [Bb*NGRP*GL*Nst];
__device__ float g_SxP [NCHUNK*Dd];
__device__ float g_SxxP[NCHUNK];
__device__ float g_lossB[Bb];

// ---------------- KP: fused projection + 2-warp split scan ------------------
// block = 64 threads = one chunk; grid = 512.
// Phase A: thread-per-token projection. Phase A2: stats split t-wise.
// Phase B: scan split n-wise (warp w owns n in [8w,8w+8)).
__global__ __launch_bounds__(64) void kP(
    const float* __restrict__ x,   const float* __restrict__ A,
    const float* __restrict__ Win, const float* __restrict__ binp,
    const float* __restrict__ Wdt, const float* __restrict__ bdt,
    const float* __restrict__ Wdtr,
    const float* __restrict__ WB,  const float* __restrict__ WC)
{
    // staging (float4): [a 256 | bd 256 | c 256 | x 512]
    __shared__ __align__(16) float4 sstage[1280];        // 20 KB
    __shared__ __align__(16) float4 sWin4[Dd*8];         // 4 KB
    __shared__ __align__(16) float4 sWB4[Dd*4], sWC4[Dd*4];
    __shared__ __align__(16) float4 sbin4[8];
    __shared__ __align__(16) float syP[2*2048];          // 16 KB partial y
    __shared__ float sweff[Dd], sA[Nst];
    __shared__ float sSx2[2][Dd];
    __shared__ float sSxx2[2];
    __shared__ float sc0;

    int tid = threadIdx.x;
    int ch  = blockIdx.x;
    int token = ch*Ll + tid;

    for (int i = tid; i < Dd*8; i += 64) sWin4[i] = ((const float4*)Win)[i];
    for (int i = tid; i < Dd*4; i += 64) { sWB4[i] = ((const float4*)WB)[i];
                                           sWC4[i] = ((const float4*)WC)[i]; }
    if (tid < 8) sbin4[tid] = ((const float4*)binp)[tid];
    if (tid < Dd) {
        float s = 0.f;
        #pragma unroll
        for (int r = 0; r < Nst; r++) s += Wdt[tid*Nst + r] * Wdtr[r];
        sweff[tid] = s;
    }
    if (tid == 32) {
        float s = 0.f;
        #pragma unroll
        for (int r = 0; r < Nst; r++) s += bdt[r] * Wdtr[r];
        sc0 = s;
    }
    if (tid >= 40 && tid < 40 + Nst) sA[tid-40] = A[tid-40];
    __syncthreads();

    // ---- phase A: projection, one token per thread ----
    float xr[32];
    {
        const float4* xg = (const float4*)x + (size_t)token*8;
        #pragma unroll
        for (int j = 0; j < 8; j++) {
            float4 v = xg[j];
            xr[j*4+0] = v.x; xr[j*4+1] = v.y; xr[j*4+2] = v.z; xr[j*4+3] = v.w;
        }
    }

    float xp[32];
    #pragma unroll
    for (int j = 0; j < 8; j++) {
        float4 b = sbin4[j];
        xp[j*4+0] = b.x; xp[j*4+1] = b.y; xp[j*4+2] = b.z; xp[j*4+3] = b.w;
    }
    #pragma unroll
    for (int k = 0; k < 32; k++) {
        float xk = xr[k];
        #pragma unroll
        for (int j = 0; j < 8; j++) {
            float4 w = sWin4[k*8+j];
            xp[j*4+0] = fmaf(xk, w.x, xp[j*4+0]);
            xp[j*4+1] = fmaf(xk, w.y, xp[j*4+1]);
            xp[j*4+2] = fmaf(xk, w.z, xp[j*4+2]);
            xp[j*4+3] = fmaf(xk, w.w, xp[j*4+3]);
        }
    }

    float zz = sc0;
    #pragma unroll
    for (int k = 0; k < 32; k++) zz = fmaf(xp[k], sweff[k], zz);
    float dt = fmaxf(zz, 0.f) + log1pf(expf(-fabsf(zz)));

    float bb[16], cc[16];
    #pragma unroll
    for (int n = 0; n < 16; n++) { bb[n] = 0.f; cc[n] = 0.f; }
    #pragma unroll
    for (int k = 0; k < 32; k++) {
        float xpk = xp[k];
        #pragma unroll
        for (int j = 0; j < 4; j++) {
            float4 wb = sWB4[k*4+j], wc = sWC4[k*4+j];
            bb[j*4+0] = fmaf(xpk, wb.x, bb[j*4+0]);
            bb[j*4+1] = fmaf(xpk, wb.y, bb[j*4+1]);
            bb[j*4+2] = fmaf(xpk, wb.z, bb[j*4+2]);
            bb[j*4+3] = fmaf(xpk, wb.w, bb[j*4+3]);
            cc[j*4+0] = fmaf(xpk, wc.x, cc[j*4+0]);
            cc[j*4+1] = fmaf(xpk, wc.y, cc[j*4+1]);
            cc[j*4+2] = fmaf(xpk, wc.z, cc[j*4+2]);
            cc[j*4+3] = fmaf(xpk, wc.w, cc[j*4+3]);
        }
    }

    #pragma unroll
    for (int j = 0; j < 4; j++) {
        sstage[      tid*4 + j] = make_float4(expf(dt*sA[j*4+0]), expf(dt*sA[j*4+1]),
                                              expf(dt*sA[j*4+2]), expf(dt*sA[j*4+3]));
        sstage[256 + tid*4 + j] = make_float4(dt*bb[j*4+0], dt*bb[j*4+1],
                                              dt*bb[j*4+2], dt*bb[j*4+3]);
        sstage[512 + tid*4 + j] = make_float4(cc[j*4+0], cc[j*4+1], cc[j*4+2], cc[j*4+3]);
    }
    #pragma unroll
    for (int j = 0; j < 8; j++)
        sstage[768 + tid*8 + j] = make_float4(xp[j*4+0], xp[j*4+1], xp[j*4+2], xp[j*4+3]);

    int warp = tid >> 5, lane = tid & 31;

    // ---- phase A2: x-stats, t-range split across warps ----
    {
        const float* xb = x + (size_t)ch*Ll*Dd + (size_t)warp*32*Dd;
        float s = 0.f, sq = 0.f;
        #pragma unroll 8
        for (int t = 0; t < 32; t++) {
            float v = xb[t*Dd + lane];
            s += v; sq = fmaf(v, v, sq);
        }
        sSx2[warp][lane] = s;
        #pragma unroll
        for (int m = 16; m >= 1; m >>= 1) sq += __shfl_xor_sync(0xffffffffu, sq, m);
        if (lane == 0) sSxx2[warp] = sq;
    }
    __syncthreads();

    // ---- phase B: scan; warp owns n in [nb, nb+8) ----
    {
        const float4* s  = sstage;
        const float*  sa = (const float*)s;              // a scalars [t*16+n]
        const float*  sc = (const float*)(s + 512);      // c scalars
        const float*  sx = (const float*)(s + 768);      // x [t*32+d]
        int nb = warp * 8;
        int np = nb + (lane & 7);                         // n for pis duty

        float h[8];
        #pragma unroll
        for (int n = 0; n < 8; n++) h[n] = 0.f;
        float pis = 1.f;

        float* syw  = syP + warp*2048;
        float* cpio = g_cpi + (size_t)ch*Ll*Nst;

        #pragma unroll 2
        for (int t = 0; t < Ll; t++) {
            float av[8], bv[8], cv[8];
            *(float4*)&av[0] = s[t*4 + warp*2 + 0];       *(float4*)&av[4] = s[t*4 + warp*2 + 1];
            *(float4*)&bv[0] = s[256 + t*4 + warp*2 + 0]; *(float4*)&bv[4] = s[256 + t*4 + warp*2 + 1];
            *(float4*)&cv[0] = s[512 + t*4 + warp*2 + 0]; *(float4*)&cv[4] = s[512 + t*4 + warp*2 + 1];
            float xv = sx[t*32 + lane];

            float y0 = 0.f, y1 = 0.f;
            #pragma unroll
            for (int n = 0; n < 8; n += 2) {
                h[n+0] = fmaf(av[n+0], h[n+0], bv[n+0]*xv); y0 = fmaf(cv[n+0], h[n+0], y0);
                h[n+1] = fmaf(av[n+1], h[n+1], bv[n+1]*xv); y1 = fmaf(cv[n+1], h[n+1], y1);
            }
            syw[t*32 + lane] = y0 + y1;

            pis *= sa[t*16 + np];
            if (lane < 8) cpio[t*Nst + np] = sc[t*16 + np] * pis;
        }

        // sL / P for this warp's n-range
        float4* outL = (float4*)g_sL + (size_t)ch*128 + lane*4 + warp*2;
        outL[0] = make_float4(h[0],h[1],h[2],h[3]);
        outL[1] = make_float4(h[4],h[5],h[6],h[7]);
        if (lane < 8) g_P[ch*Nst + np] = pis;
    }
    __syncthreads();

    // ---- combine y halves + stats, write out ----
    {
        const float4* p0 = (const float4*)syP;
        const float4* p1 = (const float4*)(syP + 2048);
        float4* yo = (float4*)g_yloc + (size_t)ch*512;
        #pragma unroll
        for (int k = 0; k < 8; k++) {
            int idx = tid + k*64;
            float4 a = p0[idx], b = p1[idx];
            yo[idx] = make_float4(a.x+b.x, a.y+b.y, a.z+b.z, a.w+b.w);
        }
    }
    if (tid < Dd)  g_SxP[ch*Dd + tid] = sSx2[0][tid] + sSx2[1][tid];
    if (tid == 32) g_SxxP[ch] = sSxx2[0] + sSxx2[1];
}

// ---------------- K3: per-batch combine + stat reduce + MLP loss ------------
__global__ __launch_bounds__(512) void k3(
    const float* __restrict__ Wd1, const float* __restrict__ bd1,
    const float* __restrict__ Wd2, const float* __restrict__ bd2,
    const float* __restrict__ Wd3, const float* __restrict__ bd3)
{
    __shared__ float sgend[NGRP*512];
    __shared__ float sPg[NGRP*Nst];
    __shared__ float sh[512];
    __shared__ float hrep[Nst], z1[HIDn], z2[HIDn], uu[Dd];
    __shared__ float sSxb[Dd], sSxxb;

    int b = blockIdx.x, off = threadIdx.x, n = off & 15;

    #pragma unroll
    for (int g = 0; g < NGRP; g++) {
        float lp[GL], ls[GL];
        #pragma unroll
        for (int j = 0; j < GL; j++) {
            int c = b*CPB + g*GL + j;
            lp[j] = g_P [c*Nst + n];
            ls[j] = g_sL[(size_t)c*512 + off];
        }
        float h = 0.f, pl = 1.f;
        #pragma unroll
        for (int j = 0; j < GL; j++) {
            int c = b*CPB + g*GL + j;
            g_hinL[(size_t)c*512 + off] = h;
            if (off < 16) g_Plp[((b*NGRP+g)*GL + j)*Nst + off] = pl;
            h  = fmaf(lp[j], h, ls[j]);
            pl *= lp[j];
        }
        sgend[g*512 + off] = h;
        if (off < 16) sPg[g*Nst + off] = pl;
    }
    __syncthreads();

    {
        float pg[NGRP], ge[NGRP];
        #pragma unroll
        for (int g = 0; g < NGRP; g++) {
            pg[g] = sPg[g*Nst + n];
            ge[g] = sgend[g*512 + off];
        }
        float h = 0.f;
        #pragma unroll
        for (int g = 0; g < NGRP; g++) {
            g_Hg[(size_t)(b*NGRP+g)*512 + off] = h;
            h = fmaf(pg[g], h, ge[g]);
        }
        sh[off] = h;
    }

    if (off < Dd) {
        float s = 0.f;
        #pragma unroll 8
        for (int k = 0; k < CPB; k++) s += g_SxP[(b*CPB + k)*Dd + off];
        sSxb[off] = s;
    } else if (off >= 32 && off < 64) {
        int l = off - 32;
        float s = g_SxxP[b*CPB + l] + g_SxxP[b*CPB + 32 + l];
        #pragma unroll
        for (int m = 16; m >= 1; m >>= 1) s += __shfl_xor_sync(0xffffffffu, s, m);
        if (l == 0) sSxxb = s;
    }
    __syncthreads();

    if (off < Nst) {
        float s = 0.f;
        #pragma unroll
        for (int d = 0; d < Dd; d++) s += sh[d*Nst + off];
        hrep[off] = s * (1.f/(float)Dd);
    }
    __syncthreads();
    if (off < HIDn) {
        float acc = bd1[off];
        #pragma unroll
        for (int nn = 0; nn < Nst; nn++) acc += hrep[nn] * Wd1[nn*HIDn + off];
        z1[off] = fmaxf(acc, 0.f);
    }
    __syncthreads();
    if (off < HIDn) {
        float acc = bd2[off];
        #pragma unroll 8
        for (int j = 0; j < HIDn; j++) acc += z1[j] * Wd2[j*HIDn + off];
        z2[off] = fmaxf(acc, 0.f);
    }
    __syncthreads();
    if (off < Dd) {
        float acc = bd3[off];
        #pragma unroll 8
        for (int j = 0; j < HIDn; j++) acc += z2[j] * Wd3[j*Dd + off];
        uu[off] = acc;
    }
    __syncthreads();
    if (off == 0) {
        float t1 = 0.f, t2 = 0.f;
        #pragma unroll
        for (int d = 0; d < Dd; d++) {
            t1 += uu[d]*uu[d];
            t2 += uu[d]*sSxb[d];
        }
        g_lossB[b] = (float)Ss * t1 - 2.f*t2 + sSxxb;
    }
}

// ---------------- K4: block-per-chunk y recombine + streaming expansion -----
__global__ __launch_bounds__(512) void k4(
    const float* __restrict__ Wout, const float* __restrict__ bout,
    float* __restrict__ out, long long out_size)
{
    __shared__ float shin[Dd*17];
    __shared__ float scpi[Ll*Nst];
    __shared__ float sy[Ll*Dd];
    __shared__ float4 sw[8], sb[8];

    int tid = threadIdx.x, ch = blockIdx.x;
    int bg = ch >> 3, j = ch & 7;

    {
        int d = tid >> 4, n = tid & 15;
        shin[d*17 + n] = fmaf(g_Plp[(bg*GL + j)*Nst + n],
                              g_Hg[(size_t)bg*512 + tid],
                              g_hinL[(size_t)ch*512 + tid]);
    }
    scpi[tid]       = g_cpi[(size_t)ch*1024 + tid];
    scpi[tid + 512] = g_cpi[(size_t)ch*1024 + 512 + tid];
    if (tid < 8)       sw[tid]   = ((const float4*)Wout)[tid];
    else if (tid < 16) sb[tid-8] = ((const float4*)bout)[tid-8];
    __syncthreads();

    #pragma unroll
    for (int k = 0; k < 4; k++) {
        int idx = tid + k*512;
        int t = idx >> 5, d = idx & 31;
        float y = g_yloc[(size_t)ch*2048 + idx];
        #pragma unroll
        for (int n = 0; n < Nst; n++)
            y = fmaf(scpi[t*Nst + n], shin[d*17 + n], y);
        sy[idx] = y;
    }
    __syncthreads();

    {
        int q = tid & 7, r0 = tid >> 3;
        float4 w4 = sw[q], b4 = sb[q];
        float4* o = (float4*)out + (size_t)ch*16384;
        #pragma unroll
        for (int k = 0; k < 32; k++) {
            int r = r0 + k*64;
            float y = sy[r];
            float4 v;
            v.x = fmaf(y, w4.x, b4.x);
            v.y = fmaf(y, w4.y, b4.y);
            v.z = fmaf(y, w4.z, b4.z);
            v.w = fmaf(y, w4.w, b4.w);
            __stcs(&o[r*8 + q], v);
        }
    }

    if (ch == 0 && tid == 0 && out_size > (long long)OUT_ELEMS) {
        float s = 0.f;
        #pragma unroll
        for (int b = 0; b < Bb; b++) s += g_lossB[b];
        out[out_size - 1] = s * (1.f/(float)(Bb*Ss));
    }
}

// ---------------- launch -----------------------------------------------------
extern "C" void kernel_launch(void* const* d_in, const int* in_sizes, int n_in,
                              void* d_out, int out_size)
{
    const float* x    = (const float*)d_in[0];
    const float* A    = (const float*)d_in[1];
    const float* Win  = (const float*)d_in[2];
    const float* binp = (const float*)d_in[3];
    const float* Wdt  = (const float*)d_in[4];
    const float* bdt  = (const float*)d_in[5];
    const float* Wdtr = (const float*)d_in[6];
    const float* WB   = (const float*)d_in[7];
    const float* WC   = (const float*)d_in[8];
    const float* Wout = (const float*)d_in[9];
    const float* bout = (const float*)d_in[10];
    const float* Wd1  = (const float*)d_in[11];
    const float* bd1  = (const float*)d_in[12];
    const float* Wd2  = (const float*)d_in[13];
    const float* bd2  = (const float*)d_in[14];
    const float* Wd3  = (const float*)d_in[15];
    const float* bd3  = (const float*)d_in[16];
    float* out = (float*)d_out;

    kP<<<NCHUNK, 64>>>(x, A, Win, binp, Wdt, bdt, Wdtr, WB, WC);
    k3<<<Bb, 512>>>(Wd1, bd1, Wd2, bd2, Wd3, bd3);
    k4<<<NCHUNK, 512>>>(Wout, bout, out, (long long)out_size);
}